// round 6
// baseline (speedup 1.0000x reference)
#include <cuda_runtime.h>
#include <cuda_bf16.h>
#include <cstdint>

// DescriptorLoss, single-pass bf16 HMMA, 64x64 warp tiles, fused final reduce.
//   dot[b,p,q] = sum_d D0[b,d,p]*D1[b,d,q]
//   loss = mean(mask ? relu(1-dot)*250 : relu(dot-0.2))

#define HW    4096
#define DDIM  128
#define NB    2
#define BM    128
#define BN    128
#define NQT   (HW / BN)          // 32
#define NPT   (HW / BM)          // 32
#define NPART (NB * NPT * NQT)   // 2048

#define LDK   136                // padded k-stride (bf16 elems), 272 B rows

#define SM_A   0
#define SM_B   (BM * LDK * 2)               // 34816
#define SM_RED (SM_B + BN * LDK * 2)        // 69632
#define SM_TOT (SM_RED + 128 * 4)           // 70144

__device__ __nv_bfloat16 g_d0t[(size_t)NB * HW * DDIM];  // [b][hw][d]
__device__ __nv_bfloat16 g_d1t[(size_t)NB * HW * DDIM];
__device__ float g_partials[NPART];
__device__ unsigned int g_count;                          // zero-init

// ---------- stage 1: convert + transpose ----------
__global__ __launch_bounds__(256)
void conv_kernel(const float* __restrict__ d0, const float* __restrict__ d1)
{
    __shared__ float tile[32][33];
    const int which = blockIdx.z & 1;
    const int b     = blockIdx.z >> 1;
    const float* src = (which ? d1 : d0) + (size_t)b * DDIM * HW;
    __nv_bfloat16* dst = (which ? g_d1t : g_d0t) + (size_t)b * HW * DDIM;

    const int hw0 = blockIdx.x * 32;
    const int dd0 = blockIdx.y * 32;
    const int tx = threadIdx.x, ty = threadIdx.y;   // 32 x 8

    #pragma unroll
    for (int j = 0; j < 4; j++)
        tile[ty + 8 * j][tx] = src[(size_t)(dd0 + ty + 8 * j) * HW + hw0 + tx];
    __syncthreads();
    #pragma unroll
    for (int j = 0; j < 4; j++)
        dst[(size_t)(hw0 + ty + 8 * j) * DDIM + dd0 + tx] =
            __float2bfloat16(tile[tx][ty + 8 * j]);
}

// ---------- stage 2: GEMM + fused loss + fused final reduce ----------
__global__ __launch_bounds__(128, 2)
void desc_loss_hmma_kernel(const int* __restrict__ mask, float* __restrict__ out)
{
    extern __shared__ char smem[];
    __nv_bfloat16* Asm = (__nv_bfloat16*)(smem + SM_A);
    __nv_bfloat16* Bsm = (__nv_bfloat16*)(smem + SM_B);
    float*         red = (float*)(smem + SM_RED);

    const int tid = threadIdx.x;
    const int wid = tid >> 5;
    const int lid = tid & 31;
    const int g   = lid >> 2;      // 0..7
    const int t   = lid & 3;       // 0..3

    const int b  = blockIdx.z;
    const int p0 = blockIdx.y * BM;
    const int q0 = blockIdx.x * BN;

    // prologue: bf16 scratch -> smem, 16B chunks (conflict-free)
    {
        const __nv_bfloat16* gA = g_d0t + (size_t)b * HW * DDIM + (size_t)p0 * DDIM;
        const __nv_bfloat16* gB = g_d1t + (size_t)b * HW * DDIM + (size_t)q0 * DDIM;
        #pragma unroll
        for (int it = 0; it < 16; it++) {
            int i = it * 128 + tid;
            int r = i >> 4;          // 0..127
            int c = i & 15;          // 16B chunk
            uint4 va = *(const uint4*)(gA + (size_t)r * DDIM + c * 8);
            uint4 vb = *(const uint4*)(gB + (size_t)r * DDIM + c * 8);
            *(uint4*)((char*)Asm + r * (LDK * 2) + c * 16) = va;
            *(uint4*)((char*)Bsm + r * (LDK * 2) + c * 16) = vb;
        }
    }
    __syncthreads();

    // 4 warps = 2(m) x 2(n), warp tile 64x64
    const int wm = wid & 1;
    const int wn = wid >> 1;

    float acc[4][8][4];
    #pragma unroll
    for (int i = 0; i < 4; i++)
        #pragma unroll
        for (int j = 0; j < 8; j++)
            #pragma unroll
            for (int u = 0; u < 4; u++)
                acc[i][j][u] = 0.0f;

    #pragma unroll
    for (int s = 0; s < 8; s++) {
        const int k0 = s * 16;
        uint32_t af[4][4], bf[8][2];
        #pragma unroll
        for (int ti = 0; ti < 4; ti++) {
            const int r0 = wm * 64 + ti * 16;
            af[ti][0] = *(const uint32_t*)&Asm[(r0 + g) * LDK + k0 + 2 * t];
            af[ti][1] = *(const uint32_t*)&Asm[(r0 + g + 8) * LDK + k0 + 2 * t];
            af[ti][2] = *(const uint32_t*)&Asm[(r0 + g) * LDK + k0 + 2 * t + 8];
            af[ti][3] = *(const uint32_t*)&Asm[(r0 + g + 8) * LDK + k0 + 2 * t + 8];
        }
        #pragma unroll
        for (int tj = 0; tj < 8; tj++) {
            const int n0 = wn * 64 + tj * 8;
            bf[tj][0] = *(const uint32_t*)&Bsm[(n0 + g) * LDK + k0 + 2 * t];
            bf[tj][1] = *(const uint32_t*)&Bsm[(n0 + g) * LDK + k0 + 2 * t + 8];
        }
        #pragma unroll
        for (int ti = 0; ti < 4; ti++)
            #pragma unroll
            for (int tj = 0; tj < 8; tj++) {
                asm volatile(
                    "mma.sync.aligned.m16n8k16.row.col.f32.bf16.bf16.f32 "
                    "{%0,%1,%2,%3}, {%4,%5,%6,%7}, {%8,%9}, {%0,%1,%2,%3};"
                    : "+f"(acc[ti][tj][0]), "+f"(acc[ti][tj][1]),
                      "+f"(acc[ti][tj][2]), "+f"(acc[ti][tj][3])
                    : "r"(af[ti][0]), "r"(af[ti][1]), "r"(af[ti][2]), "r"(af[ti][3]),
                      "r"(bf[tj][0]), "r"(bf[tj][1]));
            }
    }

    // epilogue: fused hinge loss with mask (int32)
    float lsum = 0.0f;
    {
        const int* mbase = mask + (size_t)b * HW * HW + q0;
        #pragma unroll
        for (int ti = 0; ti < 4; ti++) {
            const int pr0 = p0 + wm * 64 + ti * 16 + g;
            #pragma unroll
            for (int tj = 0; tj < 8; tj++) {
                const int qc = wn * 64 + tj * 8 + 2 * t;
                int2 m0 = *(const int2*)(mbase + (size_t)pr0 * HW + qc);
                int2 m1 = *(const int2*)(mbase + (size_t)(pr0 + 8) * HW + qc);
                float dv, pos, neg;
                dv = acc[ti][tj][0];
                pos = fmaxf(0.0f, 1.0f - dv) * 250.0f; neg = fmaxf(0.0f, dv - 0.2f);
                lsum += m0.x ? pos : neg;
                dv = acc[ti][tj][1];
                pos = fmaxf(0.0f, 1.0f - dv) * 250.0f; neg = fmaxf(0.0f, dv - 0.2f);
                lsum += m0.y ? pos : neg;
                dv = acc[ti][tj][2];
                pos = fmaxf(0.0f, 1.0f - dv) * 250.0f; neg = fmaxf(0.0f, dv - 0.2f);
                lsum += m1.x ? pos : neg;
                dv = acc[ti][tj][3];
                pos = fmaxf(0.0f, 1.0f - dv) * 250.0f; neg = fmaxf(0.0f, dv - 0.2f);
                lsum += m1.y ? pos : neg;
            }
        }
    }

    // deterministic block reduction over 128 threads
    red[tid] = lsum;
    __syncthreads();
    #pragma unroll
    for (int s = 64; s > 0; s >>= 1) {
        if (tid < s) red[tid] += red[tid + s];
        __syncthreads();
    }
    if (tid == 0)
        g_partials[(b * NPT + blockIdx.y) * NQT + blockIdx.x] = red[0];

    // last CTA performs the (fixed-order, deterministic) final reduction
    __threadfence();
    __shared__ int is_last;
    if (tid == 0) {
        unsigned int v = atomicAdd(&g_count, 1u);
        is_last = (v == NPART - 1);
    }
    __syncthreads();
    if (is_last) {
        float s = 0.0f;
        #pragma unroll
        for (int i = 0; i < NPART / 128; i++)     // 16 strided loads, fixed order
            s += g_partials[tid + i * 128];
        red[tid] = s;
        __syncthreads();
        #pragma unroll
        for (int st = 64; st > 0; st >>= 1) {
            if (tid < st) red[tid] += red[tid + st];
            __syncthreads();
        }
        if (tid == 0) {
            out[0] = red[0] * (1.0f / ((float)NB * (float)HW * (float)HW));
            g_count = 0;   // reset for next graph replay
        }
    }
}

extern "C" void kernel_launch(void* const* d_in, const int* in_sizes, int n_in,
                              void* d_out, int out_size)
{
    const float* d0   = (const float*)d_in[0];
    const float* d1   = (const float*)d_in[1];
    const int*   mask = (const int*)d_in[2];
    float*       out  = (float*)d_out;

    cudaFuncSetAttribute(desc_loss_hmma_kernel,
                         cudaFuncAttributeMaxDynamicSharedMemorySize, SM_TOT);

    conv_kernel<<<dim3(HW / 32, DDIM / 32, 2 * NB), dim3(32, 8)>>>(d0, d1);
    desc_loss_hmma_kernel<<<dim3(NQT, NPT, NB), 128, SM_TOT>>>(mask, out);
}